// round 3
// baseline (speedup 1.0000x reference)
#include <cuda_runtime.h>
#include <cuda_bf16.h>
#include <math_constants.h>

// Problem shapes (fixed by the dataset)
#define B_   16
#define CIN  256
#define COUT 256
#define H_   64
#define W_   64
#define NK   4    // kernel_number n

// Scratch (device globals: allocation-free rule)
__device__ float g_rot[B_ * NK * 81];                         // 20.7 KB
__device__ float g_W[(size_t)B_ * COUT * CIN * 9];            // 37.75 MB  [b][o][c][i]

// ---------------------------------------------------------------------------
// Kernel 1: build per-(b,n) 9x9 interpolation matrices, scaled by lambda.
// One thread per (b,n) pair (64 total). Direct transcription of the reference.
// ---------------------------------------------------------------------------
__global__ void rot_kernel(const float* __restrict__ thetas,
                           const float* __restrict__ scales,
                           const float* __restrict__ lambdas) {
    int idx = blockIdx.x * blockDim.x + threadIdx.x;
    if (idx >= B_ * NK) return;
    float t = thetas[idx];
    float s = scales[idx];
    float lam = lambdas[idx];

    float x = cosf(t) * s;
    float y = sinf(t) * s;

    float M[81];
#pragma unroll
    for (int i = 0; i < 81; i++) M[i] = 0.f;

    bool pos = (t >= 0.f);
    bool big = (s >= 1.f);
    bool m1  = (fabsf(t) <= (float)(CUDART_PI / 4.0));

    if (pos) {
        float a = x - y, b = x * y, c = x + y, d = a * c, e = a + c;
        if (m1 && big) {
            // pb1
            M[0] = a;        M[1] = 1.f - a;
            M[9+1] = 1.f-y;  M[9+2] = y;
            M[18+2] = a;     M[18+5] = 1.f-a;
            M[27+0] = y;     M[27+3] = 1.f-y;
            M[45+5] = 1.f-y; M[45+8] = y;
            M[54+3] = 1.f-a; M[54+6] = a;
            M[63+6] = y;     M[63+7] = 1.f-y;
            M[72+7] = 1.f-a; M[72+8] = a;
        } else if (m1 && !big) {
            // ps1
            M[0] = d;  M[1] = a-d;  M[3] = c-d;  M[4] = 1.f-e+d;
            M[9+1] = x-b;  M[9+2] = b;  M[9+4] = 1.f-c+b;  M[9+5] = y-b;
            M[18+1] = c-d; M[18+2] = d; M[18+4] = 1.f-e+d; M[18+5] = a-d;
            M[27+0] = b;   M[27+1] = y-b; M[27+3] = x-b;   M[27+4] = 1.f-c+b;
            M[45+4] = 1.f-c+b; M[45+5] = x-b; M[45+7] = y-b; M[45+8] = b;
            M[54+3] = a-d; M[54+4] = 1.f-e+d; M[54+6] = d;  M[54+7] = c-d;
            M[63+3] = y-b; M[63+4] = 1.f-c+b; M[63+6] = b;  M[63+7] = x-b;
            M[72+4] = 1.f-e+d; M[72+5] = c-d; M[72+7] = a-d; M[72+8] = d;
        } else {
            // pb2 (== ps2)
            M[0] = a;        M[1] = 1.f-a;
            M[9+1] = x-b;    M[9+2] = b;   M[9+4] = 1.f-c+b; M[9+5] = y-b;
            M[18+2] = a;     M[18+5] = 1.f-a;
            M[27+0] = b;     M[27+1] = y-b; M[27+3] = x-b;  M[27+4] = 1.f-c+b;
            M[45+4] = 1.f-c+b; M[45+5] = x-b; M[45+7] = y-b; M[45+8] = b;
            M[54+3] = 1.f-a; M[54+6] = a;
            M[63+3] = y-b;   M[63+4] = 1.f-c+b; M[63+6] = b; M[63+7] = x-b;
            M[72+7] = 1.f-a; M[72+8] = a;
        }
    } else {
        float yp = -y;
        float ap = x - yp, bp = x * yp, cp = x + yp, dp = ap * cp, ep = ap + cp;
        if (m1 && big) {
            // nb1
            M[0] = cp;        M[3] = 1.f-cp;
            M[9+0] = yp;      M[9+1] = 1.f-yp;
            M[18+1] = 1.f-cp; M[18+2] = cp;
            M[27+3] = 1.f-yp; M[27+6] = yp;
            M[45+2] = yp;     M[45+5] = 1.f-yp;
            M[54+6] = cp;     M[54+7] = 1.f-cp;
            M[63+7] = 1.f-yp; M[63+8] = yp;
            M[72+5] = 1.f-cp; M[72+8] = cp;
        } else if (m1 && !big) {
            // ns1
            M[0] = dp;  M[1] = cp-dp;  M[3] = ap-dp;  M[4] = 1.f-ep+dp;
            M[9+0] = bp;   M[9+1] = x-bp;  M[9+3] = yp-bp;   M[9+4] = 1.f-cp+bp;
            M[18+1] = ap-dp; M[18+2] = dp; M[18+4] = 1.f-ep+dp; M[18+5] = cp-dp;
            M[27+1] = yp-bp; M[27+2] = bp; M[27+4] = 1.f-cp+bp; M[27+5] = x-bp;
            M[45+3] = x-bp;  M[45+4] = 1.f-cp+bp; M[45+6] = bp; M[45+7] = yp-bp;
            M[54+3] = cp-dp; M[54+4] = 1.f-ep+dp; M[54+6] = dp; M[54+7] = ap-dp;
            M[63+4] = 1.f-cp+bp; M[63+5] = yp-bp; M[63+7] = x-bp; M[63+8] = bp;
            M[72+4] = 1.f-ep+dp; M[72+5] = ap-dp; M[72+7] = cp-dp; M[72+8] = dp;
        } else {
            // nb2 (== ns2)
            M[0] = cp;        M[3] = 1.f-cp;
            M[9+0] = bp;      M[9+1] = x-bp; M[9+3] = yp-bp; M[9+4] = 1.f-cp+bp;
            M[18+1] = 1.f-cp; M[18+2] = cp;
            M[27+3] = x-bp;   M[27+4] = 1.f-cp+bp; M[27+6] = bp; M[27+7] = yp-bp;
            M[45+1] = yp-bp;  M[45+2] = bp; M[45+4] = 1.f-cp+bp; M[45+5] = x-bp;
            M[54+6] = cp;     M[54+7] = 1.f-cp;
            M[63+4] = 1.f-cp+bp; M[63+5] = yp-bp; M[63+7] = x-bp; M[63+8] = bp;
            M[72+5] = 1.f-cp; M[72+8] = cp;
        }
    }
    M[40] = 1.f;  // center row, all variants

#pragma unroll
    for (int i = 0; i < 81; i++) g_rot[idx * 81 + i] = M[i] * lam;
}

// ---------------------------------------------------------------------------
// Kernel 2: per-batch transformed weights.
//   g_W[b][o][c][i] = sum_n sum_j rot[b][n][i][j] * weight[n][o][c][j]
// weight layout: [n][Cout][Cin][9]
// Grid: (256, 16); 256 threads; one thread per (o,c) pair.
// ---------------------------------------------------------------------------
__global__ void wtrans_kernel(const float* __restrict__ weight) {
    __shared__ float rs[NK * 81];
    int b = blockIdx.y;
    for (int i = threadIdx.x; i < NK * 81; i += 256)
        rs[i] = g_rot[b * NK * 81 + i];
    __syncthreads();

    int p = blockIdx.x * 256 + threadIdx.x;   // 0..65535
    int o = p >> 8;
    int c = p & 255;

    float acc[9];
#pragma unroll
    for (int i = 0; i < 9; i++) acc[i] = 0.f;

#pragma unroll
    for (int n = 0; n < NK; n++) {
        const float* wp = weight + (((size_t)n * COUT + o) * CIN + c) * 9;
        float wv[9];
#pragma unroll
        for (int j = 0; j < 9; j++) wv[j] = wp[j];
        const float* r = &rs[n * 81];
#pragma unroll
        for (int i = 0; i < 9; i++)
#pragma unroll
            for (int j = 0; j < 9; j++)
                acc[i] = fmaf(r[i * 9 + j], wv[j], acc[i]);
    }

    float* dst = g_W + (((size_t)b * COUT + o) * CIN + c) * 9;
#pragma unroll
    for (int i = 0; i < 9; i++) dst[i] = acc[i];
}

// ---------------------------------------------------------------------------
// Kernel 3: the conv. Block = 16x16 spatial tile x 64 Cout, 256 threads,
// each thread owns one spatial position and 64 Cout accumulators.
// x patch cached in registers (9 vals / channel); weights broadcast via LDS.128.
// Grid: (16 spatial tiles, 4 cout tiles, 16 batches).
// ---------------------------------------------------------------------------
__global__ void __launch_bounds__(256, 2)
conv_kernel(const float* __restrict__ x, float* __restrict__ out) {
    __shared__ float xs[18 * 18];
    __shared__ float ws[64 * 12];   // 9 weights padded to 12 for float4 loads

    const int b  = blockIdx.z;
    const int obase = blockIdx.y * 64;
    const int st = blockIdx.x;
    const int h0 = (st >> 2) * 16;
    const int w0 = (st & 3) * 16;

    const int tid = threadIdx.x;
    const int ty = tid >> 4;
    const int tx = tid & 15;
    const int h = h0 + ty;
    const int w = w0 + tx;

    float acc[64];
#pragma unroll
    for (int o = 0; o < 64; o++) acc[o] = 0.f;

    const float* xb = x + (size_t)b * CIN * H_ * W_;
    const float* Wb = g_W + ((size_t)b * COUT + obase) * CIN * 9;

    for (int c = 0; c < CIN; c++) {
        const float* xc = xb + (size_t)c * H_ * W_;
        // x patch (18x18 with halo, zero padded)
        for (int i = tid; i < 324; i += 256) {
            int r = i / 18, col = i - r * 18;
            int hh = h0 + r - 1, ww = w0 + col - 1;
            float v = 0.f;
            if (hh >= 0 && hh < H_ && ww >= 0 && ww < W_) v = xc[hh * W_ + ww];
            xs[i] = v;
        }
        // weights for this c: 64 outs x 9 taps
        for (int i = tid; i < 576; i += 256) {
            int o = i / 9, j = i - o * 9;
            ws[o * 12 + j] = Wb[((size_t)o * CIN + c) * 9 + j];
        }
        __syncthreads();

        float xv[9];
#pragma unroll
        for (int dy = 0; dy < 3; dy++)
#pragma unroll
            for (int dx = 0; dx < 3; dx++)
                xv[dy * 3 + dx] = xs[(ty + dy) * 18 + tx + dx];

#pragma unroll
        for (int o = 0; o < 64; o++) {
            const float4 wa = *(const float4*)&ws[o * 12];
            const float4 wb4 = *(const float4*)&ws[o * 12 + 4];
            const float  w8 = ws[o * 12 + 8];
            float a = acc[o];
            a = fmaf(xv[0], wa.x, a);
            a = fmaf(xv[1], wa.y, a);
            a = fmaf(xv[2], wa.z, a);
            a = fmaf(xv[3], wa.w, a);
            a = fmaf(xv[4], wb4.x, a);
            a = fmaf(xv[5], wb4.y, a);
            a = fmaf(xv[6], wb4.z, a);
            a = fmaf(xv[7], wb4.w, a);
            a = fmaf(xv[8], w8, a);
            acc[o] = a;
        }
        __syncthreads();
    }

    float* ob = out + ((size_t)(b * COUT + obase)) * (H_ * W_) + h * W_ + w;
#pragma unroll
    for (int o = 0; o < 64; o++) ob[(size_t)o * (H_ * W_)] = acc[o];
}

// ---------------------------------------------------------------------------
extern "C" void kernel_launch(void* const* d_in, const int* in_sizes, int n_in,
                              void* d_out, int out_size) {
    const float* x       = (const float*)d_in[0];   // [16,256,64,64]
    const float* thetas  = (const float*)d_in[1];   // [16,4]
    const float* scales  = (const float*)d_in[2];   // [16,4]
    const float* lambdas = (const float*)d_in[3];   // [16,4]
    const float* weight  = (const float*)d_in[4];   // [4,256,256,3,3]
    float* out = (float*)d_out;                     // [16,256,64,64]

    rot_kernel<<<1, 64>>>(thetas, scales, lambdas);
    wtrans_kernel<<<dim3(256, 16), 256>>>(weight);
    conv_kernel<<<dim3(16, 4, 16), 256>>>(x, out);
}

// round 9
// speedup vs baseline: 6.4281x; 6.4281x over previous
#include <cuda_runtime.h>
#include <cuda_bf16.h>
#include <math_constants.h>
#include <cstdint>

#define B_   16
#define CIN  256
#define COUT 256
#define H_   64
#define W_   64
#define NK   4

// ---------------------------------------------------------------------------
// Device scratch (allocation-free rule)
// ---------------------------------------------------------------------------
// A operand, mma-fragment order, tf32-rounded:
//   g_WtF[ ((b*9+tap)*32 + c8)*16 + mtg ][lane][4]
//   value(o = mtg*16 + (lane>>2) + 8*ohi, c = c8*8 + (lane&3) + 4*khi),
//   a_idx = khi*2 + ohi   (PTX m16n8k8 tf32 A layout)
__device__ __align__(1024) float g_WtF[(size_t)B_ * 9 * 32 * 16 * 128];   // 37.75 MB
// B operand, mma-fragment order, tf32-rounded:
//   g_xBF[ ((dx*16+b)*66 + h)*16384 + (c8*8 + w8)*64 + lane*2 + reg ]
//   value = x[b][c8*8 + (lane&3) + 4*reg][h-1][w8*8 + (lane>>2) - 1 + dx]
__device__ __align__(1024) float g_xBF[(size_t)3 * B_ * 66 * 16384];      // 207.6 MB
__device__ float g_rot[B_ * NK * 81];

// ---------------------------------------------------------------------------
__device__ __forceinline__ uint32_t smem_u32(const void* p) {
    uint32_t a;
    asm("{ .reg .u64 t; cvta.to.shared.u64 t, %1; cvt.u32.u64 %0, t; }" : "=r"(a) : "l"(p));
    return a;
}
__device__ __forceinline__ float tf32r(float v) {
    float o;
    asm("cvt.rna.tf32.f32 %0, %1;" : "=f"(o) : "f"(v));
    return o;
}
#define CP_ASYNC16(sm, g) \
    asm volatile("cp.async.cg.shared.global [%0], [%1], 16;" :: "r"(sm), "l"(g))
#define CP_COMMIT() asm volatile("cp.async.commit_group;" ::: "memory")
#define CP_WAIT1()  asm volatile("cp.async.wait_group 1;" ::: "memory")

__device__ __forceinline__ void mma_tf32(float* d, const uint32_t* a, const uint32_t* b) {
    asm volatile(
        "mma.sync.aligned.m16n8k8.row.col.f32.tf32.tf32.f32 "
        "{%0,%1,%2,%3}, {%4,%5,%6,%7}, {%8,%9}, {%0,%1,%2,%3};"
        : "+f"(d[0]), "+f"(d[1]), "+f"(d[2]), "+f"(d[3])
        : "r"(a[0]), "r"(a[1]), "r"(a[2]), "r"(a[3]), "r"(b[0]), "r"(b[1]));
}

// ---------------------------------------------------------------------------
// Kernel 1: per-(b,n) 9x9 interpolation matrices, scaled by lambda.
// ---------------------------------------------------------------------------
__global__ void rot_kernel(const float* __restrict__ thetas,
                           const float* __restrict__ scales,
                           const float* __restrict__ lambdas) {
    int idx = blockIdx.x * blockDim.x + threadIdx.x;
    if (idx >= B_ * NK) return;
    float t = thetas[idx];
    float s = scales[idx];
    float lam = lambdas[idx];

    float x = cosf(t) * s;
    float y = sinf(t) * s;

    float M[81];
#pragma unroll
    for (int i = 0; i < 81; i++) M[i] = 0.f;

    bool pos = (t >= 0.f);
    bool big = (s >= 1.f);
    bool m1  = (fabsf(t) <= (float)(CUDART_PI / 4.0));

    if (pos) {
        float a = x - y, b = x * y, c = x + y, d = a * c, e = a + c;
        if (m1 && big) {
            M[0] = a;        M[1] = 1.f - a;
            M[9+1] = 1.f-y;  M[9+2] = y;
            M[18+2] = a;     M[18+5] = 1.f-a;
            M[27+0] = y;     M[27+3] = 1.f-y;
            M[45+5] = 1.f-y; M[45+8] = y;
            M[54+3] = 1.f-a; M[54+6] = a;
            M[63+6] = y;     M[63+7] = 1.f-y;
            M[72+7] = 1.f-a; M[72+8] = a;
        } else if (m1 && !big) {
            M[0] = d;  M[1] = a-d;  M[3] = c-d;  M[4] = 1.f-e+d;
            M[9+1] = x-b;  M[9+2] = b;  M[9+4] = 1.f-c+b;  M[9+5] = y-b;
            M[18+1] = c-d; M[18+2] = d; M[18+4] = 1.f-e+d; M[18+5] = a-d;
            M[27+0] = b;   M[27+1] = y-b; M[27+3] = x-b;   M[27+4] = 1.f-c+b;
            M[45+4] = 1.f-c+b; M[45+5] = x-b; M[45+7] = y-b; M[45+8] = b;
            M[54+3] = a-d; M[54+4] = 1.f-e+d; M[54+6] = d;  M[54+7] = c-d;
            M[63+3] = y-b; M[63+4] = 1.f-c+b; M[63+6] = b;  M[63+7] = x-b;
            M[72+4] = 1.f-e+d; M[72+5] = c-d; M[72+7] = a-d; M[72+8] = d;
        } else {
            M[0] = a;        M[1] = 1.f-a;
            M[9+1] = x-b;    M[9+2] = b;   M[9+4] = 1.f-c+b; M[9+5] = y-b;
            M[18+2] = a;     M[18+5] = 1.f-a;
            M[27+0] = b;     M[27+1] = y-b; M[27+3] = x-b;  M[27+4] = 1.f-c+b;
            M[45+4] = 1.f-c+b; M[45+5] = x-b; M[45+7] = y-b; M[45+8] = b;
            M[54+3] = 1.f-a; M[54+6] = a;
            M[63+3] = y-b;   M[63+4] = 1.f-c+b; M[63+6] = b; M[63+7] = x-b;
            M[72+7] = 1.f-a; M[72+8] = a;
        }
    } else {
        float yp = -y;
        float ap = x - yp, bp = x * yp, cp = x + yp, dp = ap * cp, ep = ap + cp;
        if (m1 && big) {
            M[0] = cp;        M[3] = 1.f-cp;
            M[9+0] = yp;      M[9+1] = 1.f-yp;
            M[18+1] = 1.f-cp; M[18+2] = cp;
            M[27+3] = 1.f-yp; M[27+6] = yp;
            M[45+2] = yp;     M[45+5] = 1.f-yp;
            M[54+6] = cp;     M[54+7] = 1.f-cp;
            M[63+7] = 1.f-yp; M[63+8] = yp;
            M[72+5] = 1.f-cp; M[72+8] = cp;
        } else if (m1 && !big) {
            M[0] = dp;  M[1] = cp-dp;  M[3] = ap-dp;  M[4] = 1.f-ep+dp;
            M[9+0] = bp;   M[9+1] = x-bp;  M[9+3] = yp-bp;   M[9+4] = 1.f-cp+bp;
            M[18+1] = ap-dp; M[18+2] = dp; M[18+4] = 1.f-ep+dp; M[18+5] = cp-dp;
            M[27+1] = yp-bp; M[27+2] = bp; M[27+4] = 1.f-cp+bp; M[27+5] = x-bp;
            M[45+3] = x-bp;  M[45+4] = 1.f-cp+bp; M[45+6] = bp; M[45+7] = yp-bp;
            M[54+3] = cp-dp; M[54+4] = 1.f-ep+dp; M[54+6] = dp; M[54+7] = ap-dp;
            M[63+4] = 1.f-cp+bp; M[63+5] = yp-bp; M[63+7] = x-bp; M[63+8] = bp;
            M[72+4] = 1.f-ep+dp; M[72+5] = ap-dp; M[72+7] = cp-dp; M[72+8] = dp;
        } else {
            M[0] = cp;        M[3] = 1.f-cp;
            M[9+0] = bp;      M[9+1] = x-bp; M[9+3] = yp-bp; M[9+4] = 1.f-cp+bp;
            M[18+1] = 1.f-cp; M[18+2] = cp;
            M[27+3] = x-bp;   M[27+4] = 1.f-cp+bp; M[27+6] = bp; M[27+7] = yp-bp;
            M[45+1] = yp-bp;  M[45+2] = bp; M[45+4] = 1.f-cp+bp; M[45+5] = x-bp;
            M[54+6] = cp;     M[54+7] = 1.f-cp;
            M[63+4] = 1.f-cp+bp; M[63+5] = yp-bp; M[63+7] = x-bp; M[63+8] = bp;
            M[72+5] = 1.f-cp; M[72+8] = cp;
        }
    }
    M[40] = 1.f;

#pragma unroll
    for (int i = 0; i < 81; i++) g_rot[idx * 81 + i] = M[i] * lam;
}

// ---------------------------------------------------------------------------
// Kernel 2: transformed weights -> A fragment order, tf32-rounded.
// Grid (256 o, 16 b), 256 threads = c.
// ---------------------------------------------------------------------------
__global__ void wtrans_kernel(const float* __restrict__ weight) {
    __shared__ float rs[NK * 81];
    int b = blockIdx.y;
    int o = blockIdx.x;
    int c = threadIdx.x;
    for (int i = threadIdx.x; i < NK * 81; i += 256)
        rs[i] = g_rot[b * NK * 81 + i];
    __syncthreads();

    float acc[9];
#pragma unroll
    for (int i = 0; i < 9; i++) acc[i] = 0.f;

#pragma unroll
    for (int n = 0; n < NK; n++) {
        const float* wp = weight + (((size_t)n * COUT + o) * CIN + c) * 9;
        float wv[9];
#pragma unroll
        for (int j = 0; j < 9; j++) wv[j] = wp[j];
        const float* r = &rs[n * 81];
#pragma unroll
        for (int i = 0; i < 9; i++)
#pragma unroll
            for (int j = 0; j < 9; j++)
                acc[i] = fmaf(r[i * 9 + j], wv[j], acc[i]);
    }

    // fragment-position scatter
    int c8 = c >> 3;
    int klo = c & 3, khi = (c >> 2) & 1;
    int mtg = o >> 4;
    int olo = o & 7, ohi = (o >> 3) & 1;
    int lane = olo * 4 + klo;
    int aidx = khi * 2 + ohi;
#pragma unroll
    for (int tap = 0; tap < 9; tap++) {
        size_t pos = ((((size_t)(b * 9 + tap) * 32 + c8) * 16 + mtg) * 32 + lane) * 4 + aidx;
        g_WtF[pos] = tf32r(acc[tap]);
    }
}

// ---------------------------------------------------------------------------
// Kernel 3: x -> B fragment order (3 dx-shifted copies), tf32-rounded.
// Grid: 3*16*66 blocks (dx,b,h), 256 threads; each block emits 16384 floats.
// ---------------------------------------------------------------------------
__global__ void pad_kernel(const float* __restrict__ x) {
    int id = blockIdx.x;          // ((dx*16 + b)*66 + h)
    int h  = id % 66;
    int t2 = id / 66;
    int b  = t2 & 15;
    int dx = t2 >> 4;
    int hs = h - 1;               // source row
    const float* xb = x + (size_t)b * CIN * H_ * W_;
    float* dst = g_xBF + (size_t)id * 16384;

    bool hok = (hs >= 0 && hs < H_);
    for (int i = threadIdx.x; i < 16384; i += 256) {
        int c8   = i >> 9;
        int w8   = (i >> 6) & 7;
        int fi   = i & 63;
        int lane = fi >> 1;
        int reg  = fi & 1;
        int c = c8 * 8 + (lane & 3) + 4 * reg;
        int w = w8 * 8 + (lane >> 2) - 1 + dx;
        float v = 0.f;
        if (hok && w >= 0 && w < W_)
            v = tf32r(xb[((size_t)c * H_ + hs) * W_ + w]);
        dst[i] = v;
    }
}

// ---------------------------------------------------------------------------
// Kernel 4: tf32 mma.sync GEMM conv.
// CTA: 128 o x 256 n (4 rows x 64 w), 512 threads, 16 warps (2m x 8n),
// warp tile 64x32. K = 72 chunks of 32 (tap-major). 3-stage cp.async.
// Stage = A 4096 floats [k8][mtg 8][128] + B 8192 floats [k8][row 4][w8 8][64].
// ---------------------------------------------------------------------------
#define STAGE_F 12288
#define DYN_SMEM (3 * STAGE_F * 4)

__global__ void __launch_bounds__(512, 1)
conv_mma_kernel(float* __restrict__ out) {
    extern __shared__ float sm[];

    const int tid = threadIdx.x;
    const int wid = tid >> 5;
    const int lane = tid & 31;
    const int b  = blockIdx.z;
    const int my = blockIdx.y;          // m tile (0..1), m0 = my*128
    const int h0 = blockIdx.x * 4;      // output rows h0..h0+3

    const int wm = wid >> 3;            // 0..1  (warp m: 64 rows)
    const int wn = wid & 7;             // 0..7  (warp n: 32 cols)
    const int row = wn >> 1;            // output row within CTA
    const int w8b = (wn & 1) * 4;       // w8 base for this warp

    const uint32_t smb = smem_u32(sm);

    float acc[4][4][4];
#pragma unroll
    for (int i = 0; i < 4; i++)
#pragma unroll
        for (int j = 0; j < 4; j++)
#pragma unroll
            for (int k = 0; k < 4; k++) acc[i][j][k] = 0.f;

    // per-thread cp.async decode (A: 2 reps, B: 4 reps of 16B)
    const float* Abase = g_WtF + (size_t)b * 9 * 65536;   // + tap*65536
    const float* Bbase = g_xBF;

    auto issue_stage = [&](int chunk, int slot) {
        int tap = chunk >> 3;
        int q   = chunk & 7;
        int dy  = tap / 3, dx = tap - dy * 3;
        uint32_t sbase = smb + slot * (STAGE_F * 4);
        const float* Ab = Abase + (size_t)tap * 65536;
        size_t bb = ((size_t)(dx * 16 + b) * 66 + (h0 + dy)) * 16384;
#pragma unroll
        for (int r = 0; r < 2; r++) {
            int u = tid + r * 512;            // 0..1023
            int k8 = u >> 8;
            int mtgp = (u >> 5) & 7;
            int fi = (u & 31) * 4;
            const float* g = Ab + (((q * 4 + k8) * 16 + (my * 8 + mtgp)) * 128 + fi);
            CP_ASYNC16(sbase + u * 16, g);
        }
#pragma unroll
        for (int r = 0; r < 4; r++) {
            int u = tid + r * 512;            // 0..2047
            int k8 = u >> 9;
            int rw = (u >> 7) & 3;
            int w8 = (u >> 4) & 7;
            int fi = (u & 15) * 4;
            const float* g = Bbase + bb + (size_t)rw * 16384
                             + ((q * 4 + k8) * 8 + w8) * 64 + fi;
            CP_ASYNC16(sbase + 16384 + u * 16, g);
        }
    };

    issue_stage(0, 0); CP_COMMIT();
    issue_stage(1, 1); CP_COMMIT();

    for (int i = 0; i < 72; i++) {
        CP_WAIT1();
        __syncthreads();
        if (i + 2 < 72) issue_stage(i + 2, (i + 2) % 3);
        CP_COMMIT();

        const float* st = sm + (i % 3) * STAGE_F;
#pragma unroll
        for (int k8 = 0; k8 < 4; k8++) {
            uint32_t af[4][4];
#pragma unroll
            for (int ii = 0; ii < 4; ii++) {
                const uint4 v = *(const uint4*)(st + (k8 * 8 + wm * 4 + ii) * 128 + lane * 4);
                af[ii][0] = v.x; af[ii][1] = v.y; af[ii][2] = v.z; af[ii][3] = v.w;
            }
            uint32_t bf[4][2];
#pragma unroll
            for (int jj = 0; jj < 4; jj++) {
                const uint2 v = *(const uint2*)(st + 4096 + ((k8 * 4 + row) * 8 + w8b + jj) * 64 + lane * 2);
                bf[jj][0] = v.x; bf[jj][1] = v.y;
            }
#pragma unroll
            for (int ii = 0; ii < 4; ii++)
#pragma unroll
                for (int jj = 0; jj < 4; jj++)
                    mma_tf32(acc[ii][jj], af[ii], bf[jj]);
        }
    }

    // Epilogue: d frag m16n8 f32: c0,c1 at (r=t/4, col=2*(t%4)+{0,1}); c2,c3 at r+8.
    const int hout = h0 + row;
#pragma unroll
    for (int ii = 0; ii < 4; ii++) {
        int o0 = my * 128 + wm * 64 + ii * 16 + (lane >> 2);
#pragma unroll
        for (int jj = 0; jj < 4; jj++) {
            int w0 = (wn & 1) * 32 + jj * 8 + (lane & 3) * 2;
            float* p = out + ((size_t)(b * COUT + o0) * H_ + hout) * W_ + w0;
            float2 v0 = make_float2(acc[ii][jj][0], acc[ii][jj][1]);
            float2 v1 = make_float2(acc[ii][jj][2], acc[ii][jj][3]);
            *(float2*)p = v0;
            *(float2*)(p + 8 * H_ * W_) = v1;
        }
    }
}

// ---------------------------------------------------------------------------
extern "C" void kernel_launch(void* const* d_in, const int* in_sizes, int n_in,
                              void* d_out, int out_size) {
    const float* x       = (const float*)d_in[0];   // [16,256,64,64]
    const float* thetas  = (const float*)d_in[1];   // [16,4]
    const float* scales  = (const float*)d_in[2];   // [16,4]
    const float* lambdas = (const float*)d_in[3];   // [16,4]
    const float* weight  = (const float*)d_in[4];   // [4,256,256,3,3]
    float* out = (float*)d_out;                     // [16,256,64,64]

    rot_kernel<<<1, 64>>>(thetas, scales, lambdas);
    wtrans_kernel<<<dim3(256, 16), 256>>>(weight);
    pad_kernel<<<3 * B_ * 66, 256>>>(x);

    cudaFuncSetAttribute(conv_mma_kernel,
                         cudaFuncAttributeMaxDynamicSharedMemorySize, DYN_SMEM);
    conv_mma_kernel<<<dim3(16, 2, 16), 512, DYN_SMEM>>>(out);
}

// round 10
// speedup vs baseline: 7.0439x; 1.0958x over previous
#include <cuda_runtime.h>
#include <cuda_bf16.h>
#include <math_constants.h>
#include <cstdint>

#define B_   16
#define CIN  256
#define COUT 256
#define H_   64
#define W_   64
#define NK   4

// ---------------------------------------------------------------------------
// Device scratch (allocation-free rule)
// ---------------------------------------------------------------------------
// A operand, mma-fragment order, tf32-rounded:
//   g_WtF[ ((b*9+tap)*32 + c8)*16 + mtg ][lane][4]
//   value(o = mtg*16 + (lane>>2) + 8*ohi, c = c8*8 + (lane&3) + 4*khi),
//   a_idx = khi*2 + ohi   (PTX m16n8k8 tf32 A layout)
__device__ __align__(1024) float g_WtF[(size_t)B_ * 9 * 32 * 16 * 128];   // 37.75 MB
// B operand, mma-fragment order, tf32-rounded:
//   g_xBF[ ((dx*16+b)*66 + h)*16384 + (c8*8 + w8)*64 + lane*2 + reg ]
//   value = x[b][c8*8 + (lane&3) + 4*reg][h-1][w8*8 + (lane>>2) - 1 + dx]
__device__ __align__(1024) float g_xBF[(size_t)3 * B_ * 66 * 16384];      // 207.6 MB
__device__ float g_rot[B_ * NK * 81];

// ---------------------------------------------------------------------------
__device__ __forceinline__ uint32_t smem_u32(const void* p) {
    uint32_t a;
    asm("{ .reg .u64 t; cvta.to.shared.u64 t, %1; cvt.u32.u64 %0, t; }" : "=r"(a) : "l"(p));
    return a;
}
__device__ __forceinline__ float tf32r(float v) {
    float o;
    asm("cvt.rna.tf32.f32 %0, %1;" : "=f"(o) : "f"(v));
    return o;
}
#define CP_ASYNC16(sm, g) \
    asm volatile("cp.async.cg.shared.global [%0], [%1], 16;" :: "r"(sm), "l"(g))
#define CP_COMMIT() asm volatile("cp.async.commit_group;" ::: "memory")
#define CP_WAIT1()  asm volatile("cp.async.wait_group 1;" ::: "memory")

__device__ __forceinline__ void mma_tf32(float* d, const uint32_t* a, const uint32_t* b) {
    asm volatile(
        "mma.sync.aligned.m16n8k8.row.col.f32.tf32.tf32.f32 "
        "{%0,%1,%2,%3}, {%4,%5,%6,%7}, {%8,%9}, {%0,%1,%2,%3};"
        : "+f"(d[0]), "+f"(d[1]), "+f"(d[2]), "+f"(d[3])
        : "r"(a[0]), "r"(a[1]), "r"(a[2]), "r"(a[3]), "r"(b[0]), "r"(b[1]));
}

// ---------------------------------------------------------------------------
// Kernel 1: per-(b,n) 9x9 interpolation matrices, scaled by lambda.
// ---------------------------------------------------------------------------
__global__ void rot_kernel(const float* __restrict__ thetas,
                           const float* __restrict__ scales,
                           const float* __restrict__ lambdas) {
    int idx = blockIdx.x * blockDim.x + threadIdx.x;
    if (idx >= B_ * NK) return;
    float t = thetas[idx];
    float s = scales[idx];
    float lam = lambdas[idx];

    float x = cosf(t) * s;
    float y = sinf(t) * s;

    float M[81];
#pragma unroll
    for (int i = 0; i < 81; i++) M[i] = 0.f;

    bool pos = (t >= 0.f);
    bool big = (s >= 1.f);
    bool m1  = (fabsf(t) <= (float)(CUDART_PI / 4.0));

    if (pos) {
        float a = x - y, b = x * y, c = x + y, d = a * c, e = a + c;
        if (m1 && big) {
            M[0] = a;        M[1] = 1.f - a;
            M[9+1] = 1.f-y;  M[9+2] = y;
            M[18+2] = a;     M[18+5] = 1.f-a;
            M[27+0] = y;     M[27+3] = 1.f-y;
            M[45+5] = 1.f-y; M[45+8] = y;
            M[54+3] = 1.f-a; M[54+6] = a;
            M[63+6] = y;     M[63+7] = 1.f-y;
            M[72+7] = 1.f-a; M[72+8] = a;
        } else if (m1 && !big) {
            M[0] = d;  M[1] = a-d;  M[3] = c-d;  M[4] = 1.f-e+d;
            M[9+1] = x-b;  M[9+2] = b;  M[9+4] = 1.f-c+b;  M[9+5] = y-b;
            M[18+1] = c-d; M[18+2] = d; M[18+4] = 1.f-e+d; M[18+5] = a-d;
            M[27+0] = b;   M[27+1] = y-b; M[27+3] = x-b;   M[27+4] = 1.f-c+b;
            M[45+4] = 1.f-c+b; M[45+5] = x-b; M[45+7] = y-b; M[45+8] = b;
            M[54+3] = a-d; M[54+4] = 1.f-e+d; M[54+6] = d;  M[54+7] = c-d;
            M[63+3] = y-b; M[63+4] = 1.f-c+b; M[63+6] = b;  M[63+7] = x-b;
            M[72+4] = 1.f-e+d; M[72+5] = c-d; M[72+7] = a-d; M[72+8] = d;
        } else {
            M[0] = a;        M[1] = 1.f-a;
            M[9+1] = x-b;    M[9+2] = b;   M[9+4] = 1.f-c+b; M[9+5] = y-b;
            M[18+2] = a;     M[18+5] = 1.f-a;
            M[27+0] = b;     M[27+1] = y-b; M[27+3] = x-b;  M[27+4] = 1.f-c+b;
            M[45+4] = 1.f-c+b; M[45+5] = x-b; M[45+7] = y-b; M[45+8] = b;
            M[54+3] = 1.f-a; M[54+6] = a;
            M[63+3] = y-b;   M[63+4] = 1.f-c+b; M[63+6] = b; M[63+7] = x-b;
            M[72+7] = 1.f-a; M[72+8] = a;
        }
    } else {
        float yp = -y;
        float ap = x - yp, bp = x * yp, cp = x + yp, dp = ap * cp, ep = ap + cp;
        if (m1 && big) {
            M[0] = cp;        M[3] = 1.f-cp;
            M[9+0] = yp;      M[9+1] = 1.f-yp;
            M[18+1] = 1.f-cp; M[18+2] = cp;
            M[27+3] = 1.f-yp; M[27+6] = yp;
            M[45+2] = yp;     M[45+5] = 1.f-yp;
            M[54+6] = cp;     M[54+7] = 1.f-cp;
            M[63+7] = 1.f-yp; M[63+8] = yp;
            M[72+5] = 1.f-cp; M[72+8] = cp;
        } else if (m1 && !big) {
            M[0] = dp;  M[1] = cp-dp;  M[3] = ap-dp;  M[4] = 1.f-ep+dp;
            M[9+0] = bp;   M[9+1] = x-bp;  M[9+3] = yp-bp;   M[9+4] = 1.f-cp+bp;
            M[18+1] = ap-dp; M[18+2] = dp; M[18+4] = 1.f-ep+dp; M[18+5] = cp-dp;
            M[27+1] = yp-bp; M[27+2] = bp; M[27+4] = 1.f-cp+bp; M[27+5] = x-bp;
            M[45+3] = x-bp;  M[45+4] = 1.f-cp+bp; M[45+6] = bp; M[45+7] = yp-bp;
            M[54+3] = cp-dp; M[54+4] = 1.f-ep+dp; M[54+6] = dp; M[54+7] = ap-dp;
            M[63+4] = 1.f-cp+bp; M[63+5] = yp-bp; M[63+7] = x-bp; M[63+8] = bp;
            M[72+4] = 1.f-ep+dp; M[72+5] = ap-dp; M[72+7] = cp-dp; M[72+8] = dp;
        } else {
            M[0] = cp;        M[3] = 1.f-cp;
            M[9+0] = bp;      M[9+1] = x-bp; M[9+3] = yp-bp; M[9+4] = 1.f-cp+bp;
            M[18+1] = 1.f-cp; M[18+2] = cp;
            M[27+3] = x-bp;   M[27+4] = 1.f-cp+bp; M[27+6] = bp; M[27+7] = yp-bp;
            M[45+1] = yp-bp;  M[45+2] = bp; M[45+4] = 1.f-cp+bp; M[45+5] = x-bp;
            M[54+6] = cp;     M[54+7] = 1.f-cp;
            M[63+4] = 1.f-cp+bp; M[63+5] = yp-bp; M[63+7] = x-bp; M[63+8] = bp;
            M[72+5] = 1.f-cp; M[72+8] = cp;
        }
    }
    M[40] = 1.f;

#pragma unroll
    for (int i = 0; i < 81; i++) g_rot[idx * 81 + i] = M[i] * lam;
}

// ---------------------------------------------------------------------------
// Kernel 2: transformed weights -> A fragment order, tf32-rounded.
// ---------------------------------------------------------------------------
__global__ void wtrans_kernel(const float* __restrict__ weight) {
    __shared__ float rs[NK * 81];
    int b = blockIdx.y;
    int o = blockIdx.x;
    int c = threadIdx.x;
    for (int i = threadIdx.x; i < NK * 81; i += 256)
        rs[i] = g_rot[b * NK * 81 + i];
    __syncthreads();

    float acc[9];
#pragma unroll
    for (int i = 0; i < 9; i++) acc[i] = 0.f;

#pragma unroll
    for (int n = 0; n < NK; n++) {
        const float* wp = weight + (((size_t)n * COUT + o) * CIN + c) * 9;
        float wv[9];
#pragma unroll
        for (int j = 0; j < 9; j++) wv[j] = wp[j];
        const float* r = &rs[n * 81];
#pragma unroll
        for (int i = 0; i < 9; i++)
#pragma unroll
            for (int j = 0; j < 9; j++)
                acc[i] = fmaf(r[i * 9 + j], wv[j], acc[i]);
    }

    int c8 = c >> 3;
    int klo = c & 3, khi = (c >> 2) & 1;
    int mtg = o >> 4;
    int olo = o & 7, ohi = (o >> 3) & 1;
    int lane = olo * 4 + klo;
    int aidx = khi * 2 + ohi;
#pragma unroll
    for (int tap = 0; tap < 9; tap++) {
        size_t pos = ((((size_t)(b * 9 + tap) * 32 + c8) * 16 + mtg) * 32 + lane) * 4 + aidx;
        g_WtF[pos] = tf32r(acc[tap]);
    }
}

// ---------------------------------------------------------------------------
// Kernel 3: x -> B fragment order (3 dx-shifted copies), tf32-rounded.
// ---------------------------------------------------------------------------
__global__ void pad_kernel(const float* __restrict__ x) {
    int id = blockIdx.x;          // ((dx*16 + b)*66 + h)
    int h  = id % 66;
    int t2 = id / 66;
    int b  = t2 & 15;
    int dx = t2 >> 4;
    int hs = h - 1;
    const float* xb = x + (size_t)b * CIN * H_ * W_;
    float* dst = g_xBF + (size_t)id * 16384;

    bool hok = (hs >= 0 && hs < H_);
    for (int i = threadIdx.x; i < 16384; i += 256) {
        int c8   = i >> 9;
        int w8   = (i >> 6) & 7;
        int fi   = i & 63;
        int lane = fi >> 1;
        int reg  = fi & 1;
        int c = c8 * 8 + (lane & 3) + 4 * reg;
        int w = w8 * 8 + (lane >> 2) - 1 + dx;
        float v = 0.f;
        if (hok && w >= 0 && w < W_)
            v = tf32r(xb[((size_t)c * H_ + hs) * W_ + w]);
        dst[i] = v;
    }
}

// ---------------------------------------------------------------------------
// Kernel 4: tf32 mma.sync GEMM conv.
// CTA: 128 o x 128 n (2 rows x 64 w), 256 threads, 8 warps (2m x 4n),
// warp tile 64x32. K = 72 chunks of 32 (tap-major). 3-stage cp.async,
// 32KB/stage -> 96KB smem -> 2 CTAs/SM (the round's lever: cross-CTA
// overlap hides barrier + LDS stalls that held tensor pipe at 60%).
// ---------------------------------------------------------------------------
#define STAGE_F 8192
#define DYN_SMEM (3 * STAGE_F * 4)

__global__ void __launch_bounds__(256, 2)
conv_mma_kernel(float* __restrict__ out) {
    extern __shared__ float sm[];

    const int tid = threadIdx.x;
    const int wid = tid >> 5;
    const int lane = tid & 31;
    const int b  = blockIdx.z;
    const int my = blockIdx.y;          // m tile (0..1), m0 = my*128
    const int h0 = blockIdx.x * 2;      // output rows h0..h0+1

    const int wm = wid >> 2;            // 0..1  (warp m: 64 rows)
    const int wn = wid & 3;             // 0..3  (warp n: 32 cols)
    const int row = wn >> 1;            // output row within CTA (0..1)
    const int w8b = (wn & 1) * 4;       // w8 base for this warp

    const uint32_t smb = smem_u32(sm);

    float acc[4][4][4];
#pragma unroll
    for (int i = 0; i < 4; i++)
#pragma unroll
        for (int j = 0; j < 4; j++)
#pragma unroll
            for (int k = 0; k < 4; k++) acc[i][j][k] = 0.f;

    const float* Abase = g_WtF + (size_t)b * 9 * 65536;
    const float* Bbase = g_xBF;

    auto issue_stage = [&](int chunk, int slot) {
        int tap = chunk >> 3;
        int q   = chunk & 7;
        int dy  = tap / 3, dx = tap - dy * 3;
        uint32_t sbase = smb + slot * (STAGE_F * 4);
        const float* Ab = Abase + (size_t)tap * 65536;
        size_t bb = ((size_t)(dx * 16 + b) * 66 + (h0 + dy)) * 16384;
        // A: 4096 floats = [k8 4][mtg 8][128]
#pragma unroll
        for (int r = 0; r < 4; r++) {
            int u = tid + r * 256;            // 0..1023
            int k8 = u >> 8;
            int mtgp = (u >> 5) & 7;
            int fi = (u & 31) * 4;
            const float* g = Ab + (((q * 4 + k8) * 16 + (my * 8 + mtgp)) * 128 + fi);
            CP_ASYNC16(sbase + u * 16, g);
        }
        // B: 4096 floats = [k8 4][row 2][w8 8][64]
#pragma unroll
        for (int r = 0; r < 4; r++) {
            int u = tid + r * 256;            // 0..1023
            int k8 = u >> 8;
            int rw = (u >> 7) & 1;
            int w8 = (u >> 4) & 7;
            int fi = (u & 15) * 4;
            const float* g = Bbase + bb + (size_t)rw * 16384
                             + ((q * 4 + k8) * 8 + w8) * 64 + fi;
            CP_ASYNC16(sbase + 16384 + u * 16, g);
        }
    };

    issue_stage(0, 0); CP_COMMIT();
    issue_stage(1, 1); CP_COMMIT();

    for (int i = 0; i < 72; i++) {
        CP_WAIT1();
        __syncthreads();
        if (i + 2 < 72) issue_stage(i + 2, (i + 2) % 3);
        CP_COMMIT();

        const float* st = sm + (i % 3) * STAGE_F;
#pragma unroll
        for (int k8 = 0; k8 < 4; k8++) {
            uint32_t af[4][4];
#pragma unroll
            for (int ii = 0; ii < 4; ii++) {
                const uint4 v = *(const uint4*)(st + (k8 * 8 + wm * 4 + ii) * 128 + lane * 4);
                af[ii][0] = v.x; af[ii][1] = v.y; af[ii][2] = v.z; af[ii][3] = v.w;
            }
            uint32_t bf[4][2];
#pragma unroll
            for (int jj = 0; jj < 4; jj++) {
                const uint2 v = *(const uint2*)(st + 4096 + ((k8 * 2 + row) * 8 + w8b + jj) * 64 + lane * 2);
                bf[jj][0] = v.x; bf[jj][1] = v.y;
            }
#pragma unroll
            for (int ii = 0; ii < 4; ii++)
#pragma unroll
                for (int jj = 0; jj < 4; jj++)
                    mma_tf32(acc[ii][jj], af[ii], bf[jj]);
        }
    }

    // Epilogue
    const int hout = h0 + row;
#pragma unroll
    for (int ii = 0; ii < 4; ii++) {
        int o0 = my * 128 + wm * 64 + ii * 16 + (lane >> 2);
#pragma unroll
        for (int jj = 0; jj < 4; jj++) {
            int w0 = (wn & 1) * 32 + jj * 8 + (lane & 3) * 2;
            float* p = out + ((size_t)(b * COUT + o0) * H_ + hout) * W_ + w0;
            float2 v0 = make_float2(acc[ii][jj][0], acc[ii][jj][1]);
            float2 v1 = make_float2(acc[ii][jj][2], acc[ii][jj][3]);
            *(float2*)p = v0;
            *(float2*)(p + 8 * H_ * W_) = v1;
        }
    }
}

// ---------------------------------------------------------------------------
extern "C" void kernel_launch(void* const* d_in, const int* in_sizes, int n_in,
                              void* d_out, int out_size) {
    const float* x       = (const float*)d_in[0];   // [16,256,64,64]
    const float* thetas  = (const float*)d_in[1];   // [16,4]
    const float* scales  = (const float*)d_in[2];   // [16,4]
    const float* lambdas = (const float*)d_in[3];   // [16,4]
    const float* weight  = (const float*)d_in[4];   // [4,256,256,3,3]
    float* out = (float*)d_out;                     // [16,256,64,64]

    rot_kernel<<<1, 64>>>(thetas, scales, lambdas);
    wtrans_kernel<<<dim3(256, 16), 256>>>(weight);
    pad_kernel<<<3 * B_ * 66, 256>>>(x);

    cudaFuncSetAttribute(conv_mma_kernel,
                         cudaFuncAttributeMaxDynamicSharedMemorySize, DYN_SMEM);
    conv_mma_kernel<<<dim3(32, 2, 16), 256, DYN_SMEM>>>(out);
}

// round 11
// speedup vs baseline: 11.7099x; 1.6624x over previous
#include <cuda_runtime.h>
#include <cuda_fp16.h>
#include <math_constants.h>
#include <cstdint>

#define B_   16
#define CIN  256
#define COUT 256
#define H_   64
#define W_   64
#define NK   4

// ---------------------------------------------------------------------------
// Device scratch (allocation-free rule)
// ---------------------------------------------------------------------------
// A operand (fp16, m16n8k16 fragment order):
//   per (b,tap): [cchunk 8][kstep 2][mtile 16][lane 32][8 halves]  = 65536 halves
//   A tile 16o x 16c; thread lane, reg r(0..3), half t:
//     row(o&15) = (lane>>2) + 8*(r&1); col(c&15) = (lane&3)*2 + t + 8*(r>>1)
__device__ __align__(1024) __half g_WtFh[(size_t)B_ * 9 * 65536];          // 18.9 MB
// B operand (fp16 fragment order), 3 dx-shifted padded copies:
//   per (dx,b,h): [cchunk 8][kstep 2][w8 8][lane 32][4 halves] = 16384 halves
//   B tile 16k x 8n: n(w&7) = lane>>2; k(c&15) = (lane&3)*2 + t + 8*reg
__device__ __align__(1024) __half g_xBFh[(size_t)3 * B_ * 66 * 16384];     // 103.8 MB
__device__ float g_rot[B_ * NK * 81];

// ---------------------------------------------------------------------------
__device__ __forceinline__ uint32_t smem_u32(const void* p) {
    uint32_t a;
    asm("{ .reg .u64 t; cvta.to.shared.u64 t, %1; cvt.u32.u64 %0, t; }" : "=r"(a) : "l"(p));
    return a;
}
#define CP_ASYNC16(sm, g) \
    asm volatile("cp.async.cg.shared.global [%0], [%1], 16;" :: "r"(sm), "l"(g))
#define CP_COMMIT() asm volatile("cp.async.commit_group;" ::: "memory")
#define CP_WAIT2()  asm volatile("cp.async.wait_group 2;" ::: "memory")

__device__ __forceinline__ void mma_f16(float* d, const uint32_t* a, const uint32_t* b) {
    asm volatile(
        "mma.sync.aligned.m16n8k16.row.col.f32.f16.f16.f32 "
        "{%0,%1,%2,%3}, {%4,%5,%6,%7}, {%8,%9}, {%0,%1,%2,%3};"
        : "+f"(d[0]), "+f"(d[1]), "+f"(d[2]), "+f"(d[3])
        : "r"(a[0]), "r"(a[1]), "r"(a[2]), "r"(a[3]), "r"(b[0]), "r"(b[1]));
}

// ---------------------------------------------------------------------------
// Kernel 1: per-(b,n) 9x9 interpolation matrices, scaled by lambda.
// ---------------------------------------------------------------------------
__global__ void rot_kernel(const float* __restrict__ thetas,
                           const float* __restrict__ scales,
                           const float* __restrict__ lambdas) {
    int idx = blockIdx.x * blockDim.x + threadIdx.x;
    if (idx >= B_ * NK) return;
    float t = thetas[idx];
    float s = scales[idx];
    float lam = lambdas[idx];

    float x = cosf(t) * s;
    float y = sinf(t) * s;

    float M[81];
#pragma unroll
    for (int i = 0; i < 81; i++) M[i] = 0.f;

    bool pos = (t >= 0.f);
    bool big = (s >= 1.f);
    bool m1  = (fabsf(t) <= (float)(CUDART_PI / 4.0));

    if (pos) {
        float a = x - y, b = x * y, c = x + y, d = a * c, e = a + c;
        if (m1 && big) {
            M[0] = a;        M[1] = 1.f - a;
            M[9+1] = 1.f-y;  M[9+2] = y;
            M[18+2] = a;     M[18+5] = 1.f-a;
            M[27+0] = y;     M[27+3] = 1.f-y;
            M[45+5] = 1.f-y; M[45+8] = y;
            M[54+3] = 1.f-a; M[54+6] = a;
            M[63+6] = y;     M[63+7] = 1.f-y;
            M[72+7] = 1.f-a; M[72+8] = a;
        } else if (m1 && !big) {
            M[0] = d;  M[1] = a-d;  M[3] = c-d;  M[4] = 1.f-e+d;
            M[9+1] = x-b;  M[9+2] = b;  M[9+4] = 1.f-c+b;  M[9+5] = y-b;
            M[18+1] = c-d; M[18+2] = d; M[18+4] = 1.f-e+d; M[18+5] = a-d;
            M[27+0] = b;   M[27+1] = y-b; M[27+3] = x-b;   M[27+4] = 1.f-c+b;
            M[45+4] = 1.f-c+b; M[45+5] = x-b; M[45+7] = y-b; M[45+8] = b;
            M[54+3] = a-d; M[54+4] = 1.f-e+d; M[54+6] = d;  M[54+7] = c-d;
            M[63+3] = y-b; M[63+4] = 1.f-c+b; M[63+6] = b;  M[63+7] = x-b;
            M[72+4] = 1.f-e+d; M[72+5] = c-d; M[72+7] = a-d; M[72+8] = d;
        } else {
            M[0] = a;        M[1] = 1.f-a;
            M[9+1] = x-b;    M[9+2] = b;   M[9+4] = 1.f-c+b; M[9+5] = y-b;
            M[18+2] = a;     M[18+5] = 1.f-a;
            M[27+0] = b;     M[27+1] = y-b; M[27+3] = x-b;  M[27+4] = 1.f-c+b;
            M[45+4] = 1.f-c+b; M[45+5] = x-b; M[45+7] = y-b; M[45+8] = b;
            M[54+3] = 1.f-a; M[54+6] = a;
            M[63+3] = y-b;   M[63+4] = 1.f-c+b; M[63+6] = b; M[63+7] = x-b;
            M[72+7] = 1.f-a; M[72+8] = a;
        }
    } else {
        float yp = -y;
        float ap = x - yp, bp = x * yp, cp = x + yp, dp = ap * cp, ep = ap + cp;
        if (m1 && big) {
            M[0] = cp;        M[3] = 1.f-cp;
            M[9+0] = yp;      M[9+1] = 1.f-yp;
            M[18+1] = 1.f-cp; M[18+2] = cp;
            M[27+3] = 1.f-yp; M[27+6] = yp;
            M[45+2] = yp;     M[45+5] = 1.f-yp;
            M[54+6] = cp;     M[54+7] = 1.f-cp;
            M[63+7] = 1.f-yp; M[63+8] = yp;
            M[72+5] = 1.f-cp; M[72+8] = cp;
        } else if (m1 && !big) {
            M[0] = dp;  M[1] = cp-dp;  M[3] = ap-dp;  M[4] = 1.f-ep+dp;
            M[9+0] = bp;   M[9+1] = x-bp;  M[9+3] = yp-bp;   M[9+4] = 1.f-cp+bp;
            M[18+1] = ap-dp; M[18+2] = dp; M[18+4] = 1.f-ep+dp; M[18+5] = cp-dp;
            M[27+1] = yp-bp; M[27+2] = bp; M[27+4] = 1.f-cp+bp; M[27+5] = x-bp;
            M[45+3] = x-bp;  M[45+4] = 1.f-cp+bp; M[45+6] = bp; M[45+7] = yp-bp;
            M[54+3] = cp-dp; M[54+4] = 1.f-ep+dp; M[54+6] = dp; M[54+7] = ap-dp;
            M[63+4] = 1.f-cp+bp; M[63+5] = yp-bp; M[63+7] = x-bp; M[63+8] = bp;
            M[72+4] = 1.f-ep+dp; M[72+5] = ap-dp; M[72+7] = cp-dp; M[72+8] = dp;
        } else {
            M[0] = cp;        M[3] = 1.f-cp;
            M[9+0] = bp;      M[9+1] = x-bp; M[9+3] = yp-bp; M[9+4] = 1.f-cp+bp;
            M[18+1] = 1.f-cp; M[18+2] = cp;
            M[27+3] = x-bp;   M[27+4] = 1.f-cp+bp; M[27+6] = bp; M[27+7] = yp-bp;
            M[45+1] = yp-bp;  M[45+2] = bp; M[45+4] = 1.f-cp+bp; M[45+5] = x-bp;
            M[54+6] = cp;     M[54+7] = 1.f-cp;
            M[63+4] = 1.f-cp+bp; M[63+5] = yp-bp; M[63+7] = x-bp; M[63+8] = bp;
            M[72+5] = 1.f-cp; M[72+8] = cp;
        }
    }
    M[40] = 1.f;

#pragma unroll
    for (int i = 0; i < 81; i++) g_rot[idx * 81 + i] = M[i] * lam;
}

// ---------------------------------------------------------------------------
// Kernel 2: transformed weights -> A fp16 fragment order.
// Grid (256 o, 16 b), 256 threads = c.
// ---------------------------------------------------------------------------
__global__ void wtrans_kernel(const float* __restrict__ weight) {
    __shared__ float rs[NK * 81];
    int b = blockIdx.y;
    int o = blockIdx.x;
    int c = threadIdx.x;
    for (int i = threadIdx.x; i < NK * 81; i += 256)
        rs[i] = g_rot[b * NK * 81 + i];
    __syncthreads();

    float acc[9];
#pragma unroll
    for (int i = 0; i < 9; i++) acc[i] = 0.f;

#pragma unroll
    for (int n = 0; n < NK; n++) {
        const float* wp = weight + (((size_t)n * COUT + o) * CIN + c) * 9;
        float wv[9];
#pragma unroll
        for (int j = 0; j < 9; j++) wv[j] = wp[j];
        const float* r = &rs[n * 81];
#pragma unroll
        for (int i = 0; i < 9; i++)
#pragma unroll
            for (int j = 0; j < 9; j++)
                acc[i] = fmaf(r[i * 9 + j], wv[j], acc[i]);
    }

    // fragment scatter: A tile 16x16, thread lane/reg/half decode
    int cchunk = c >> 5;
    int kstep  = (c >> 4) & 1;
    int mtile  = o >> 4;
    int lane   = (o & 7) * 4 + ((c >> 1) & 3);
    int r      = ((o >> 3) & 1) | (((c >> 3) & 1) << 1);
    int t      = c & 1;
    size_t base = (size_t)(b * 9) * 65536
                + ((size_t)(cchunk * 2 + kstep) * 16 + mtile) * 256 + lane * 8 + r * 2 + t;
#pragma unroll
    for (int tap = 0; tap < 9; tap++)
        g_WtFh[base + (size_t)tap * 65536] = __float2half(acc[tap]);
}

// ---------------------------------------------------------------------------
// Kernel 3: x -> B fp16 fragment order (3 dx-shifted padded copies).
// Grid: 3*16*66 blocks (dx,b,h), 256 threads; 8192 uint32 units per block,
// each unit = 2 halves = 2 consecutive channels at one w.
// ---------------------------------------------------------------------------
__global__ void pad_kernel(const float* __restrict__ x) {
    int id = blockIdx.x;          // ((dx*16 + b)*66 + h)
    int h  = id % 66;
    int t2 = id / 66;
    int b  = t2 & 15;
    int dx = t2 >> 4;
    int hs = h - 1;
    const float* xb = x + (size_t)b * CIN * H_ * W_;
    uint32_t* dst = (uint32_t*)(g_xBFh + (size_t)id * 16384);

    bool hok = (hs >= 0 && hs < H_);
    for (int u = threadIdx.x; u < 8192; u += 256) {
        int reg    = u & 1;
        int lane   = (u >> 1) & 31;
        int w8     = (u >> 6) & 7;
        int kstep  = (u >> 9) & 1;
        int cchunk = u >> 10;
        int c = cchunk * 32 + kstep * 16 + reg * 8 + (lane & 3) * 2;
        int w = w8 * 8 + (lane >> 2) - 1 + dx;
        float v0 = 0.f, v1 = 0.f;
        if (hok && w >= 0 && w < W_) {
            v0 = xb[((size_t)c * H_ + hs) * W_ + w];
            v1 = xb[((size_t)(c + 1) * H_ + hs) * W_ + w];
        }
        __half2 hv = __floats2half2_rn(v0, v1);
        dst[u] = *(uint32_t*)&hv;
    }
}

// ---------------------------------------------------------------------------
// Kernel 4: fp16 mma.sync (m16n8k16) GEMM conv.
// CTA: 128 o x 128 n (2 rows x 64 w), 256 threads, 8 warps (2m x 4n),
// warp tile 64x32. K = 72 chunks of 32 c (tap-major; 2 k16 steps each).
// 4-stage cp.async pipeline, 16KB/stage -> 64KB smem, 2 CTAs/SM.
// Stage: A [kstep 2][mtileLocal 8][lane 32][16B] = 8KB,
//        B [kstep 2][row 2][w8 8][lane 32][8B]   = 8KB.
// ---------------------------------------------------------------------------
#define STAGE_U32 4096                  // uint32 per stage (16KB)
#define DYN_SMEM (4 * STAGE_U32 * 4)

__global__ void __launch_bounds__(256, 2)
conv_mma_kernel(float* __restrict__ out) {
    extern __shared__ uint32_t sm[];

    const int tid = threadIdx.x;
    const int wid = tid >> 5;
    const int lane = tid & 31;
    const int b  = blockIdx.z;
    const int my = blockIdx.y;          // m tile (0..1), m0 = my*128
    const int h0 = blockIdx.x * 2;      // output rows h0..h0+1

    const int wm = wid >> 2;            // 0..1  (warp m: 64 rows)
    const int wn = wid & 3;             // 0..3  (warp n: 32 cols)
    const int row = wn >> 1;            // output row within CTA (0..1)
    const int w8b = (wn & 1) * 4;       // w8 base for this warp

    const uint32_t smb = smem_u32(sm);

    float acc[4][4][4];
#pragma unroll
    for (int i = 0; i < 4; i++)
#pragma unroll
        for (int j = 0; j < 4; j++)
#pragma unroll
            for (int k = 0; k < 4; k++) acc[i][j][k] = 0.f;

    const __half* Abase = g_WtFh + (size_t)b * 9 * 65536;
    const __half* Bbase = g_xBFh;

    auto issue_stage = [&](int chunk, int slot) {
        int tap = chunk >> 3;
        int q   = chunk & 7;                          // cchunk
        int dy  = tap / 3, dx = tap - dy * 3;
        uint32_t sbase = smb + slot * (STAGE_U32 * 4);
        const __half* Ab = Abase + (size_t)tap * 65536;
        size_t bhbase = ((size_t)(dx * 16 + b) * 66 + (h0 + dy)) * 16384;
        // A: 512 x 16B
#pragma unroll
        for (int r = 0; r < 2; r++) {
            int u = tid + r * 256;                    // 0..511
            int kstep = u >> 8;
            int mtl   = (u >> 5) & 7;
            int ln    = u & 31;
            const __half* g = Ab + ((size_t)(q * 2 + kstep) * 16 + (my * 8 + mtl)) * 256 + ln * 8;
            CP_ASYNC16(sbase + u * 16, g);
        }
        // B: 512 x 16B (two h rows)
#pragma unroll
        for (int r = 0; r < 2; r++) {
            int u = tid + r * 256;                    // 0..511
            int kstep = u >> 8;
            int rw    = (u >> 7) & 1;
            int w8    = (u >> 4) & 7;
            int lp    = u & 15;                       // lane pair
            const __half* g = Bbase + bhbase + (size_t)rw * 16384
                              + ((size_t)(q * 2 + kstep) * 8 + w8) * 128 + lp * 8;
            CP_ASYNC16(sbase + 8192 + u * 16, g);
        }
    };

    issue_stage(0, 0); CP_COMMIT();
    issue_stage(1, 1); CP_COMMIT();
    issue_stage(2, 2); CP_COMMIT();

    for (int i = 0; i < 72; i++) {
        CP_WAIT2();
        __syncthreads();
        if (i + 3 < 72) issue_stage(i + 3, (i + 3) & 3);
        CP_COMMIT();

        const uint32_t* st = sm + (i & 3) * STAGE_U32;
#pragma unroll
        for (int kstep = 0; kstep < 2; kstep++) {
            uint32_t af[4][4];
#pragma unroll
            for (int ii = 0; ii < 4; ii++) {
                const uint4 v = *(const uint4*)(st + ((kstep * 8 + wm * 4 + ii) * 32 + lane) * 4);
                af[ii][0] = v.x; af[ii][1] = v.y; af[ii][2] = v.z; af[ii][3] = v.w;
            }
            uint32_t bf[4][2];
#pragma unroll
            for (int jj = 0; jj < 4; jj++) {
                const uint2 v = *(const uint2*)(st + 2048 +
                                 (((kstep * 2 + row) * 8 + w8b + jj) * 32 + lane) * 2);
                bf[jj][0] = v.x; bf[jj][1] = v.y;
            }
#pragma unroll
            for (int ii = 0; ii < 4; ii++)
#pragma unroll
                for (int jj = 0; jj < 4; jj++)
                    mma_f16(acc[ii][jj], af[ii], bf[jj]);
        }
    }

    // Epilogue: m16n8 f32 D frag: c0,c1 at (r=lane/4, col=2*(lane%4)+{0,1}); c2,c3 at r+8.
    const int hout = h0 + row;
#pragma unroll
    for (int ii = 0; ii < 4; ii++) {
        int o0 = my * 128 + wm * 64 + ii * 16 + (lane >> 2);
#pragma unroll
        for (int jj = 0; jj < 4; jj++) {
            int w0 = (wn & 1) * 32 + jj * 8 + (lane & 3) * 2;
            float* p = out + ((size_t)(b * COUT + o0) * H_ + hout) * W_ + w0;
            *(float2*)p = make_float2(acc[ii][jj][0], acc[ii][jj][1]);
            *(float2*)(p + 8 * H_ * W_) = make_float2(acc[ii][jj][2], acc[ii][jj][3]);
        }
    }
}

// ---------------------------------------------------------------------------
extern "C" void kernel_launch(void* const* d_in, const int* in_sizes, int n_in,
                              void* d_out, int out_size) {
    const float* x       = (const float*)d_in[0];   // [16,256,64,64]
    const float* thetas  = (const float*)d_in[1];   // [16,4]
    const float* scales  = (const float*)d_in[2];   // [16,4]
    const float* lambdas = (const float*)d_in[3];   // [16,4]
    const float* weight  = (const float*)d_in[4];   // [4,256,256,3,3]
    float* out = (float*)d_out;                     // [16,256,64,64]

    rot_kernel<<<1, 64>>>(thetas, scales, lambdas);
    wtrans_kernel<<<dim3(256, 16), 256>>>(weight);
    pad_kernel<<<3 * B_ * 66, 256>>>(x);

    cudaFuncSetAttribute(conv_mma_kernel,
                         cudaFuncAttributeMaxDynamicSharedMemorySize, DYN_SMEM);
    conv_mma_kernel<<<dim3(32, 2, 16), 256, DYN_SMEM>>>(out);
}

// round 12
// speedup vs baseline: 14.0142x; 1.1968x over previous
#include <cuda_runtime.h>
#include <cuda_fp16.h>
#include <math_constants.h>
#include <cstdint>

#define B_   16
#define CIN  256
#define COUT 256
#define H_   64
#define W_   64
#define NK   4

// ---------------------------------------------------------------------------
// Device scratch (allocation-free rule)
// ---------------------------------------------------------------------------
// A operand (fp16, m16n8k16 fragment order):
//   per (b,tap): [cchunk 8][kstep 2][mtile 16][lane 32][8 halves] = 65536 halves
__device__ __align__(1024) __half g_WtFh[(size_t)B_ * 9 * 65536];          // 18.9 MB
// B operand (fp16 fragment order), 3 dx-shifted padded copies:
//   per (dx,b,h): [cchunk 8][kstep 2][w8 8][lane 32][4 halves] = 16384 halves
__device__ __align__(1024) __half g_xBFh[(size_t)3 * B_ * 66 * 16384];     // 103.8 MB
__device__ float g_rot[B_ * NK * 81];

// ---------------------------------------------------------------------------
__device__ __forceinline__ uint32_t smem_u32(const void* p) {
    uint32_t a;
    asm("{ .reg .u64 t; cvta.to.shared.u64 t, %1; cvt.u32.u64 %0, t; }" : "=r"(a) : "l"(p));
    return a;
}
#define CP_ASYNC16(sm, g) \
    asm volatile("cp.async.cg.shared.global [%0], [%1], 16;" :: "r"(sm), "l"(g))
#define CP_COMMIT() asm volatile("cp.async.commit_group;" ::: "memory")
#define CP_WAIT2()  asm volatile("cp.async.wait_group 2;" ::: "memory")

__device__ __forceinline__ void mma_f16(float* d, const uint32_t* a, const uint32_t* b) {
    asm volatile(
        "mma.sync.aligned.m16n8k16.row.col.f32.f16.f16.f32 "
        "{%0,%1,%2,%3}, {%4,%5,%6,%7}, {%8,%9}, {%0,%1,%2,%3};"
        : "+f"(d[0]), "+f"(d[1]), "+f"(d[2]), "+f"(d[3])
        : "r"(a[0]), "r"(a[1]), "r"(a[2]), "r"(a[3]), "r"(b[0]), "r"(b[1]));
}

// ---------------------------------------------------------------------------
// Kernel 1: per-(b,n) 9x9 interpolation matrices, scaled by lambda.
// ---------------------------------------------------------------------------
__global__ void rot_kernel(const float* __restrict__ thetas,
                           const float* __restrict__ scales,
                           const float* __restrict__ lambdas) {
    int idx = blockIdx.x * blockDim.x + threadIdx.x;
    if (idx >= B_ * NK) return;
    float t = thetas[idx];
    float s = scales[idx];
    float lam = lambdas[idx];

    float x = cosf(t) * s;
    float y = sinf(t) * s;

    float M[81];
#pragma unroll
    for (int i = 0; i < 81; i++) M[i] = 0.f;

    bool pos = (t >= 0.f);
    bool big = (s >= 1.f);
    bool m1  = (fabsf(t) <= (float)(CUDART_PI / 4.0));

    if (pos) {
        float a = x - y, b = x * y, c = x + y, d = a * c, e = a + c;
        if (m1 && big) {
            M[0] = a;        M[1] = 1.f - a;
            M[9+1] = 1.f-y;  M[9+2] = y;
            M[18+2] = a;     M[18+5] = 1.f-a;
            M[27+0] = y;     M[27+3] = 1.f-y;
            M[45+5] = 1.f-y; M[45+8] = y;
            M[54+3] = 1.f-a; M[54+6] = a;
            M[63+6] = y;     M[63+7] = 1.f-y;
            M[72+7] = 1.f-a; M[72+8] = a;
        } else if (m1 && !big) {
            M[0] = d;  M[1] = a-d;  M[3] = c-d;  M[4] = 1.f-e+d;
            M[9+1] = x-b;  M[9+2] = b;  M[9+4] = 1.f-c+b;  M[9+5] = y-b;
            M[18+1] = c-d; M[18+2] = d; M[18+4] = 1.f-e+d; M[18+5] = a-d;
            M[27+0] = b;   M[27+1] = y-b; M[27+3] = x-b;   M[27+4] = 1.f-c+b;
            M[45+4] = 1.f-c+b; M[45+5] = x-b; M[45+7] = y-b; M[45+8] = b;
            M[54+3] = a-d; M[54+4] = 1.f-e+d; M[54+6] = d;  M[54+7] = c-d;
            M[63+3] = y-b; M[63+4] = 1.f-c+b; M[63+6] = b;  M[63+7] = x-b;
            M[72+4] = 1.f-e+d; M[72+5] = c-d; M[72+7] = a-d; M[72+8] = d;
        } else {
            M[0] = a;        M[1] = 1.f-a;
            M[9+1] = x-b;    M[9+2] = b;   M[9+4] = 1.f-c+b; M[9+5] = y-b;
            M[18+2] = a;     M[18+5] = 1.f-a;
            M[27+0] = b;     M[27+1] = y-b; M[27+3] = x-b;  M[27+4] = 1.f-c+b;
            M[45+4] = 1.f-c+b; M[45+5] = x-b; M[45+7] = y-b; M[45+8] = b;
            M[54+3] = 1.f-a; M[54+6] = a;
            M[63+3] = y-b;   M[63+4] = 1.f-c+b; M[63+6] = b; M[63+7] = x-b;
            M[72+7] = 1.f-a; M[72+8] = a;
        }
    } else {
        float yp = -y;
        float ap = x - yp, bp = x * yp, cp = x + yp, dp = ap * cp, ep = ap + cp;
        if (m1 && big) {
            M[0] = cp;        M[3] = 1.f-cp;
            M[9+0] = yp;      M[9+1] = 1.f-yp;
            M[18+1] = 1.f-cp; M[18+2] = cp;
            M[27+3] = 1.f-yp; M[27+6] = yp;
            M[45+2] = yp;     M[45+5] = 1.f-yp;
            M[54+6] = cp;     M[54+7] = 1.f-cp;
            M[63+7] = 1.f-yp; M[63+8] = yp;
            M[72+5] = 1.f-cp; M[72+8] = cp;
        } else if (m1 && !big) {
            M[0] = dp;  M[1] = cp-dp;  M[3] = ap-dp;  M[4] = 1.f-ep+dp;
            M[9+0] = bp;   M[9+1] = x-bp;  M[9+3] = yp-bp;   M[9+4] = 1.f-cp+bp;
            M[18+1] = ap-dp; M[18+2] = dp; M[18+4] = 1.f-ep+dp; M[18+5] = cp-dp;
            M[27+1] = yp-bp; M[27+2] = bp; M[27+4] = 1.f-cp+bp; M[27+5] = x-bp;
            M[45+3] = x-bp;  M[45+4] = 1.f-cp+bp; M[45+6] = bp; M[45+7] = yp-bp;
            M[54+3] = cp-dp; M[54+4] = 1.f-ep+dp; M[54+6] = dp; M[54+7] = ap-dp;
            M[63+4] = 1.f-cp+bp; M[63+5] = yp-bp; M[63+7] = x-bp; M[63+8] = bp;
            M[72+4] = 1.f-ep+dp; M[72+5] = ap-dp; M[72+7] = cp-dp; M[72+8] = dp;
        } else {
            M[0] = cp;        M[3] = 1.f-cp;
            M[9+0] = bp;      M[9+1] = x-bp; M[9+3] = yp-bp; M[9+4] = 1.f-cp+bp;
            M[18+1] = 1.f-cp; M[18+2] = cp;
            M[27+3] = x-bp;   M[27+4] = 1.f-cp+bp; M[27+6] = bp; M[27+7] = yp-bp;
            M[45+1] = yp-bp;  M[45+2] = bp; M[45+4] = 1.f-cp+bp; M[45+5] = x-bp;
            M[54+6] = cp;     M[54+7] = 1.f-cp;
            M[63+4] = 1.f-cp+bp; M[63+5] = yp-bp; M[63+7] = x-bp; M[63+8] = bp;
            M[72+5] = 1.f-cp; M[72+8] = cp;
        }
    }
    M[40] = 1.f;

#pragma unroll
    for (int i = 0; i < 81; i++) g_rot[idx * 81 + i] = M[i] * lam;
}

// ---------------------------------------------------------------------------
// Kernel 2: transformed weights -> A fp16 fragment order.
// ---------------------------------------------------------------------------
__global__ void wtrans_kernel(const float* __restrict__ weight) {
    __shared__ float rs[NK * 81];
    int b = blockIdx.y;
    int o = blockIdx.x;
    int c = threadIdx.x;
    for (int i = threadIdx.x; i < NK * 81; i += 256)
        rs[i] = g_rot[b * NK * 81 + i];
    __syncthreads();

    float acc[9];
#pragma unroll
    for (int i = 0; i < 9; i++) acc[i] = 0.f;

#pragma unroll
    for (int n = 0; n < NK; n++) {
        const float* wp = weight + (((size_t)n * COUT + o) * CIN + c) * 9;
        float wv[9];
#pragma unroll
        for (int j = 0; j < 9; j++) wv[j] = wp[j];
        const float* r = &rs[n * 81];
#pragma unroll
        for (int i = 0; i < 9; i++)
#pragma unroll
            for (int j = 0; j < 9; j++)
                acc[i] = fmaf(r[i * 9 + j], wv[j], acc[i]);
    }

    int cchunk = c >> 5;
    int kstep  = (c >> 4) & 1;
    int mtile  = o >> 4;
    int lane   = (o & 7) * 4 + ((c >> 1) & 3);
    int r      = ((o >> 3) & 1) | (((c >> 3) & 1) << 1);
    int t      = c & 1;
    size_t base = (size_t)(b * 9) * 65536
                + ((size_t)(cchunk * 2 + kstep) * 16 + mtile) * 256 + lane * 8 + r * 2 + t;
#pragma unroll
    for (int tap = 0; tap < 9; tap++)
        g_WtFh[base + (size_t)tap * 65536] = __float2half(acc[tap]);
}

// ---------------------------------------------------------------------------
// Kernel 3: x -> B fp16 fragment order, 3 dx copies emitted from ONE smem
// staging pass. Block = (b,h): 1056 blocks, 256 threads.
// Phase 1: coalesced read of x[b][*][h-1][*] into smem (fp16, padded rows).
// Phase 2: fragment scatter, coalesced gmem writes, x read only once.
// ---------------------------------------------------------------------------
__global__ void pad_kernel(const float* __restrict__ x) {
    __shared__ __half sx[256 * 66];       // [c][w], row stride 66 halves
    int id = blockIdx.x;                  // b*66 + h
    int h = id % 66;
    int b = id / 66;
    int hs = h - 1;
    bool hok = (hs >= 0 && hs < H_);
    int tid = threadIdx.x;

    if (hok) {
        int wl = tid & 63;
        int cs = tid >> 6;                // 4 c-rows per iteration
        for (int c0 = 0; c0 < 256; c0 += 4) {
            int c = c0 + cs;
            float v = x[((size_t)(b * CIN + c) * H_ + hs) * W_ + wl];
            sx[c * 66 + wl] = __float2half(v);
        }
    }
    __syncthreads();

    for (int dx = 0; dx < 3; dx++) {
        uint32_t* dst = (uint32_t*)(g_xBFh + ((size_t)(dx * 16 + b) * 66 + h) * 16384);
        for (int u = tid; u < 8192; u += 256) {
            int reg    = u & 1;
            int lane   = (u >> 1) & 31;
            int w8     = (u >> 6) & 7;
            int kstep  = (u >> 9) & 1;
            int cchunk = u >> 10;
            int c = cchunk * 32 + kstep * 16 + reg * 8 + (lane & 3) * 2;
            int w = w8 * 8 + (lane >> 2) - 1 + dx;
            uint32_t val = 0;
            if (hok && w >= 0 && w < W_) {
                __half2 hv;
                hv.x = sx[c * 66 + w];
                hv.y = sx[(c + 1) * 66 + w];
                val = *(uint32_t*)&hv;
            }
            dst[u] = val;
        }
    }
}

// ---------------------------------------------------------------------------
// Kernel 4: fp16 mma.sync (m16n8k16) GEMM conv.
// CTA: 128 o x 128 n (2 rows x 64 w), 128 threads, 4 warps (2m x 2n),
// warp tile 64 x 64 (1.5x better smem-reuse than 64x32 -> crossbar unbound).
// K = 72 chunks of 32 c (tap-major; 2 k16 steps each).
// 4-stage cp.async pipeline, 16KB/stage -> 64KB smem, 2 CTAs/SM.
// Stage: A [kstep 2][mtileLocal 8][lane 32][16B] = 8KB,
//        B [kstep 2][row 2][w8 8][lane 32][8B]   = 8KB.
// ---------------------------------------------------------------------------
#define STAGE_U32 4096                  // uint32 per stage (16KB)
#define DYN_SMEM (4 * STAGE_U32 * 4)

__global__ void __launch_bounds__(128, 2)
conv_mma_kernel(float* __restrict__ out) {
    extern __shared__ uint32_t sm[];

    const int tid = threadIdx.x;
    const int wid = tid >> 5;
    const int lane = tid & 31;
    const int b  = blockIdx.z;
    const int my = blockIdx.y;          // m tile (0..1), m0 = my*128
    const int h0 = blockIdx.x * 2;      // output rows h0..h0+1

    const int wm = wid >> 1;            // 0..1  (warp m: 64 rows)
    const int row = wid & 1;            // warp n: one full output row (64 w)

    const uint32_t smb = smem_u32(sm);

    float acc[4][8][4];
#pragma unroll
    for (int i = 0; i < 4; i++)
#pragma unroll
        for (int j = 0; j < 8; j++)
#pragma unroll
            for (int k = 0; k < 4; k++) acc[i][j][k] = 0.f;

    const __half* Abase = g_WtFh + (size_t)b * 9 * 65536;
    const __half* Bbase = g_xBFh;

    auto issue_stage = [&](int chunk, int slot) {
        int tap = chunk >> 3;
        int q   = chunk & 7;                          // cchunk
        int dy  = tap / 3, dx = tap - dy * 3;
        uint32_t sbase = smb + slot * (STAGE_U32 * 4);
        const __half* Ab = Abase + (size_t)tap * 65536;
        size_t bhbase = ((size_t)(dx * 16 + b) * 66 + (h0 + dy)) * 16384;
        // A: 512 x 16B
#pragma unroll
        for (int r = 0; r < 4; r++) {
            int u = tid + r * 128;                    // 0..511
            int kstep = u >> 8;
            int mtl   = (u >> 5) & 7;
            int ln    = u & 31;
            const __half* g = Ab + ((size_t)(q * 2 + kstep) * 16 + (my * 8 + mtl)) * 256 + ln * 8;
            CP_ASYNC16(sbase + u * 16, g);
        }
        // B: 512 x 16B (two h rows)
#pragma unroll
        for (int r = 0; r < 4; r++) {
            int u = tid + r * 128;                    // 0..511
            int kstep = u >> 8;
            int rw    = (u >> 7) & 1;
            int w8    = (u >> 4) & 7;
            int lp    = u & 15;                       // lane pair
            const __half* g = Bbase + bhbase + (size_t)rw * 16384
                              + ((size_t)(q * 2 + kstep) * 8 + w8) * 128 + lp * 8;
            CP_ASYNC16(sbase + 8192 + u * 16, g);
        }
    };

    issue_stage(0, 0); CP_COMMIT();
    issue_stage(1, 1); CP_COMMIT();
    issue_stage(2, 2); CP_COMMIT();

    for (int i = 0; i < 72; i++) {
        CP_WAIT2();
        __syncthreads();
        if (i + 3 < 72) issue_stage(i + 3, (i + 3) & 3);
        CP_COMMIT();

        const uint32_t* st = sm + (i & 3) * STAGE_U32;
#pragma unroll
        for (int kstep = 0; kstep < 2; kstep++) {
            uint32_t af[4][4];
#pragma unroll
            for (int ii = 0; ii < 4; ii++) {
                const uint4 v = *(const uint4*)(st + ((kstep * 8 + wm * 4 + ii) * 32 + lane) * 4);
                af[ii][0] = v.x; af[ii][1] = v.y; af[ii][2] = v.z; af[ii][3] = v.w;
            }
#pragma unroll
            for (int jj = 0; jj < 8; jj++) {
                uint32_t bf[2];
                const uint2 v = *(const uint2*)(st + 2048 +
                                 (((kstep * 2 + row) * 8 + jj) * 32 + lane) * 2);
                bf[0] = v.x; bf[1] = v.y;
#pragma unroll
                for (int ii = 0; ii < 4; ii++)
                    mma_f16(acc[ii][jj], af[ii], bf);
            }
        }
    }

    // Epilogue: m16n8 f32 D frag: c0,c1 at (r=lane/4, col=2*(lane%4)+{0,1}); c2,c3 at r+8.
    const int hout = h0 + row;
#pragma unroll
    for (int ii = 0; ii < 4; ii++) {
        int o0 = my * 128 + wm * 64 + ii * 16 + (lane >> 2);
#pragma unroll
        for (int jj = 0; jj < 8; jj++) {
            int w0 = jj * 8 + (lane & 3) * 2;
            float* p = out + ((size_t)(b * COUT + o0) * H_ + hout) * W_ + w0;
            *(float2*)p = make_float2(acc[ii][jj][0], acc[ii][jj][1]);
            *(float2*)(p + 8 * H_ * W_) = make_float2(acc[ii][jj][2], acc[ii][jj][3]);
        }
    }
}

// ---------------------------------------------------------------------------
extern "C" void kernel_launch(void* const* d_in, const int* in_sizes, int n_in,
                              void* d_out, int out_size) {
    const float* x       = (const float*)d_in[0];   // [16,256,64,64]
    const float* thetas  = (const float*)d_in[1];   // [16,4]
    const float* scales  = (const float*)d_in[2];   // [16,4]
    const float* lambdas = (const float*)d_in[3];   // [16,4]
    const float* weight  = (const float*)d_in[4];   // [4,256,256,3,3]
    float* out = (float*)d_out;                     // [16,256,64,64]

    rot_kernel<<<1, 64>>>(thetas, scales, lambdas);
    wtrans_kernel<<<dim3(256, 16), 256>>>(weight);
    pad_kernel<<<B_ * 66, 256>>>(x);

    cudaFuncSetAttribute(conv_mma_kernel,
                         cudaFuncAttributeMaxDynamicSharedMemorySize, DYN_SMEM);
    conv_mma_kernel<<<dim3(32, 2, 16), 128, DYN_SMEM>>>(out);
}